// round 8
// baseline (speedup 1.0000x reference)
#include <cuda_runtime.h>
#include <mma.h>
#include <cstdint>
#include <climits>

using namespace nvcuda;

// ----------------------------------------------------------------------------
// BagModel, warp-autonomous wmma tf32 + cp.async + warp-segmented atomics:
//   each warp: 16-row tile. D = X[16,32] @ W1[32,64] (tf32, fp32 acc)
//   epilogue: per-row s = sum_j relu(D+b1[j])*W2[j]; then a segmented
//   warp scan over (sorted) bag ids so only ONE atomic per bag-segment
//   per tile is issued (kills L2 same-address atomic serialization).
// ----------------------------------------------------------------------------

#define MAX_BAGS (1 << 18)
__device__ float g_sum[MAX_BAGS];
__device__ float g_cnt[MAX_BAGS];

__global__ void zero_kernel(int nbags) {
    int i = blockIdx.x * blockDim.x + threadIdx.x;
    if (i < nbags) { g_sum[i] = 0.0f; g_cnt[i] = 0.0f; }
}

__device__ __forceinline__ uint32_t smem_u32(const void* p) {
    uint32_t a;
    asm("{ .reg .u64 t; cvta.to.shared.u64 t, %1; cvt.u32.u64 %0, t; }"
        : "=r"(a) : "l"(p));
    return a;
}
#define CP_ASYNC16(dst, src) \
    asm volatile("cp.async.ca.shared.global [%0], [%1], 16;" \
                 :: "r"(dst), "l"(src) : "memory")
#define CP_COMMIT() asm volatile("cp.async.commit_group;" ::: "memory")
#define CP_WAIT1()  asm volatile("cp.async.wait_group 1;" ::: "memory")

static constexpr int LDA = 36;
static constexpr int LDD = 68;
static constexpr int LDB = 68;
static constexpr int NWARP = 4;

__global__ __launch_bounds__(128, 4) void mlp_wmma_kernel(
    const float* __restrict__ x,     // [n, 32]
    const int*   __restrict__ ids,   // [n] sorted
    const float* __restrict__ W1,    // [32, 64]
    const float* __restrict__ b1,    // [64]
    const float* __restrict__ W2,    // [64]
    int n, int nwt)
{
    __shared__ __align__(16) float sA[NWARP][2][16 * LDA];
    __shared__ __align__(16) float sD[NWARP][16 * LDD];
    __shared__ __align__(16) float sB[32 * LDB];
    __shared__ float2 sBW[64];

    const int tid  = threadIdx.x;
    const int lane = tid & 31;
    const int warp = tid >> 5;

    for (int idx = tid; idx < 32 * 64; idx += 128) {
        int k = idx >> 6, nn = idx & 63;
        sB[k * LDB + nn] = wmma::__float_to_tf32(W1[k * 64 + nn]);
    }
    if (tid < 64) sBW[tid] = make_float2(b1[tid], W2[tid]);
    __syncthreads();

    wmma::fragment<wmma::matrix_b, 16, 16, 8, wmma::precision::tf32,
                   wmma::row_major> bf[4][4];
    #pragma unroll
    for (int k = 0; k < 4; k++)
        #pragma unroll
        for (int nt = 0; nt < 4; nt++)
            wmma::load_matrix_sync(bf[k][nt], sB + (k * 8) * LDB + nt * 16, LDB);

    const char* xb = reinterpret_cast<const char*>(x);
    float* dbuf = &sD[warp][0];
    const int gwarp   = blockIdx.x * NWARP + warp;
    const int gstride = gridDim.x * NWARP;
    const int erow  = lane >> 1;
    const int ehalf = lane & 1;

    auto prefetch = [&](int wt, int pb) {
        if (wt < nwt) {
            const int row0 = wt * 16;
            if (row0 + 16 <= n) {
                #pragma unroll
                for (int t = 0; t < 4; t++) {
                    int slot = lane + 32 * t;
                    uint32_t dst = smem_u32(&sA[warp][pb][(slot >> 3) * LDA +
                                                          (slot & 7) * 4]);
                    const char* src = xb + ((size_t)wt * 2048 + (size_t)slot * 16);
                    CP_ASYNC16(dst, src);
                }
            } else {
                #pragma unroll
                for (int t = 0; t < 4; t++) {
                    int slot = lane + 32 * t;
                    int row = slot >> 3, q = slot & 7;
                    float4 v = make_float4(0.f, 0.f, 0.f, 0.f);
                    if (row0 + row < n)
                        v = reinterpret_cast<const float4*>(x)[(size_t)wt * 128 + slot];
                    *reinterpret_cast<float4*>(&sA[warp][pb][row * LDA + q * 4]) = v;
                }
            }
        }
        CP_COMMIT();
    };

    int pb = 0;
    prefetch(gwarp, 0);

    for (int wt = gwarp; wt < nwt; wt += gstride) {
        prefetch(wt + gstride, pb ^ 1);
        CP_WAIT1();
        __syncwarp();

        const float* abuf = &sA[warp][pb][0];
        const int row0 = wt * 16;

        wmma::fragment<wmma::accumulator, 16, 16, 8, float> acc[4];
        #pragma unroll
        for (int nt = 0; nt < 4; nt++) wmma::fill_fragment(acc[nt], 0.0f);

        #pragma unroll
        for (int k = 0; k < 4; k++) {
            wmma::fragment<wmma::matrix_a, 16, 16, 8, wmma::precision::tf32,
                           wmma::row_major> af;
            wmma::load_matrix_sync(af, abuf + k * 8, LDA);
            #pragma unroll
            for (int e = 0; e < af.num_elements; e++)
                af.x[e] = wmma::__float_to_tf32(af.x[e]);
            #pragma unroll
            for (int nt = 0; nt < 4; nt++)
                wmma::mma_sync(acc[nt], af, bf[k][nt], acc[nt]);
        }

        #pragma unroll
        for (int nt = 0; nt < 4; nt++)
            wmma::store_matrix_sync(dbuf + nt * 16, acc[nt], LDD,
                                    wmma::mem_row_major);
        __syncwarp();

        // per-row relu + W2 reduction (lane pair per row)
        float s0 = 0.f, s1 = 0.f, s2 = 0.f, s3 = 0.f;
        const float* rp = dbuf + erow * LDD + ehalf * 32;
        #pragma unroll
        for (int j4 = 0; j4 < 8; j4++) {
            float4 d = *reinterpret_cast<const float4*>(rp + j4 * 4);
            int j = ehalf * 32 + j4 * 4;
            float2 bw;
            float* sacc = (j4 & 3) == 0 ? &s0 : (j4 & 3) == 1 ? &s1
                        : (j4 & 3) == 2 ? &s2 : &s3;
            bw = sBW[j + 0]; *sacc = fmaf(fmaxf(d.x + bw.x, 0.f), bw.y, *sacc);
            bw = sBW[j + 1]; *sacc = fmaf(fmaxf(d.y + bw.x, 0.f), bw.y, *sacc);
            bw = sBW[j + 2]; *sacc = fmaf(fmaxf(d.z + bw.x, 0.f), bw.y, *sacc);
            bw = sBW[j + 3]; *sacc = fmaf(fmaxf(d.w + bw.x, 0.f), bw.y, *sacc);
        }
        float s = (s0 + s1) + (s2 + s3);
        s += __shfl_xor_sync(0xFFFFFFFF, s, 1);   // both lanes of pair hold row sum

        // ---- warp-segmented reduction over sorted bag ids ----
        // move row r's sum to lane r (r = 0..15)
        float sv = __shfl_sync(0xFFFFFFFF, s, (lane & 15) << 1);
        int   row   = row0 + (lane & 15);
        bool  valid = (lane < 16) && (row < n);
        int   bag   = valid ? ids[row] : INT_MAX;
        float cv    = valid ? 1.0f : 0.0f;
        if (!valid) sv = 0.0f;

        #pragma unroll
        for (int d = 1; d < 16; d <<= 1) {
            float ts = __shfl_up_sync(0xFFFFFFFF, sv, d);
            float tc = __shfl_up_sync(0xFFFFFFFF, cv, d);
            int   tb = __shfl_up_sync(0xFFFFFFFF, bag, d);
            if (lane >= d && tb == bag) { sv += ts; cv += tc; }
        }
        int bnext = __shfl_down_sync(0xFFFFFFFF, bag, 1);
        if (valid && (lane == 15 || bnext != bag)) {
            atomicAdd(&g_sum[bag], sv);
            atomicAdd(&g_cnt[bag], cv);
        }
        __syncwarp();
        pb ^= 1;
    }
}

__global__ void finalize_kernel(float* __restrict__ out,
                                const float* __restrict__ b2, int nbags)
{
    int b = blockIdx.x * blockDim.x + threadIdx.x;
    if (b < nbags) {
        float c = g_cnt[b];
        c = (c > 0.0f) ? c : 1.0f;
        out[b] = g_sum[b] / c + b2[0];
    }
}

extern "C" void kernel_launch(void* const* d_in, const int* in_sizes, int n_in,
                              void* d_out, int out_size)
{
    const float* x   = (const float*)d_in[0];
    const int*   ids = (const int*)  d_in[1];
    const float* W1  = (const float*)d_in[2];
    const float* b1  = (const float*)d_in[3];
    const float* W2  = (const float*)d_in[4];
    const float* b2  = (const float*)d_in[5];
    float* out = (float*)d_out;

    int n     = in_sizes[1];
    int nbags = out_size;
    int nwt   = (n + 15) / 16;

    zero_kernel<<<(nbags + 255) / 256, 256>>>(nbags);

    int grid = 148 * 4;
    int maxg = (nwt + NWARP - 1) / NWARP;
    if (grid > maxg) grid = maxg;
    mlp_wmma_kernel<<<grid, 32 * NWARP>>>(x, ids, W1, b1, W2, n, nwt);

    finalize_kernel<<<(nbags + 255) / 256, 256>>>(out, b2, nbags);
}

// round 10
// speedup vs baseline: 1.1283x; 1.1283x over previous
#include <cuda_runtime.h>
#include <cuda_fp16.h>
#include <mma.h>
#include <cstdint>
#include <climits>

using namespace nvcuda;

// ----------------------------------------------------------------------------
// BagModel, warp-autonomous wmma fp16 (m16n16k16) + prefetch + segmented atomics
//   each warp: 16-row tile. D = X[16,32] @ W1[32,64] (fp16 in, fp32 acc)
//   B fragments in registers for the whole kernel.
//   epilogue: bulk acc->SMEM, per-row s = sum_j relu(D+b1[j])*W2[j] (fp32),
//   warp-segmented scan over sorted bag ids -> ~1 atomic per bag-segment.
// ----------------------------------------------------------------------------

#define MAX_BAGS (1 << 18)
__device__ float g_sum[MAX_BAGS];
__device__ float g_cnt[MAX_BAGS];

__global__ void zero_kernel(int nbags) {
    int i = blockIdx.x * blockDim.x + threadIdx.x;
    if (i < nbags) { g_sum[i] = 0.0f; g_cnt[i] = 0.0f; }
}

static constexpr int LDAH = 40;   // A half-stride (halves): 80B rows
static constexpr int LDBH = 72;   // B half-stride
static constexpr int LDD  = 68;   // D f32 scratch stride
static constexpr int NWARP = 4;

__device__ __forceinline__ uint32_t h2_bits(half2 h) {
    return *reinterpret_cast<uint32_t*>(&h);
}

__global__ __launch_bounds__(128, 4) void mlp_wmma_kernel(
    const float* __restrict__ x,     // [n, 32]
    const int*   __restrict__ ids,   // [n] sorted
    const float* __restrict__ W1,    // [32, 64]
    const float* __restrict__ b1,    // [64]
    const float* __restrict__ W2,    // [64]
    int n, int nwt)
{
    __shared__ __align__(16) half  sAh[NWARP][2][16 * LDAH];  // 10.2 KB
    __shared__ __align__(16) float sD[NWARP][16 * LDD];       // 17.4 KB
    __shared__ __align__(16) half  sBh[32 * LDBH];            //  4.6 KB
    __shared__ float2 sBW[64];

    const int tid  = threadIdx.x;
    const int lane = tid & 31;
    const int warp = tid >> 5;

    for (int idx = tid; idx < 32 * 64; idx += 128) {
        int k = idx >> 6, nn = idx & 63;
        sBh[k * LDBH + nn] = __float2half_rn(W1[idx]);
    }
    if (tid < 64) sBW[tid] = make_float2(b1[tid], W2[tid]);
    __syncthreads();

    // B fragments: registers for the whole kernel (2 k-steps x 4 n-tiles)
    wmma::fragment<wmma::matrix_b, 16, 16, 16, half, wmma::row_major> bf[2][4];
    #pragma unroll
    for (int k = 0; k < 2; k++)
        #pragma unroll
        for (int nt = 0; nt < 4; nt++)
            wmma::load_matrix_sync(bf[k][nt], sBh + (k * 16) * LDBH + nt * 16, LDBH);

    float* dbuf = &sD[warp][0];
    const float4* xg = reinterpret_cast<const float4*>(x);
    const int gwarp   = blockIdx.x * NWARP + warp;
    const int gstride = gridDim.x * NWARP;
    const int erow  = lane >> 1;
    const int ehalf = lane & 1;

    // ---- prefetch first tile into registers ----
    float4 pf[4];
    if (gwarp < nwt) {
        #pragma unroll
        for (int t = 0; t < 4; t++) {
            int slot = lane + 32 * t;
            int row = slot >> 3;
            pf[t] = make_float4(0.f, 0.f, 0.f, 0.f);
            if (gwarp * 16 + row < n) pf[t] = xg[(size_t)gwarp * 128 + slot];
        }
    }

    int pb = 0;
    for (int wt = gwarp; wt < nwt; wt += gstride) {
        const int row0 = wt * 16;

        // ---- stage prefetched A: fp32 -> fp16, STS.64 ----
        half* abuf = &sAh[warp][pb][0];
        #pragma unroll
        for (int t = 0; t < 4; t++) {
            int slot = lane + 32 * t;
            int row = slot >> 3, q = slot & 7;
            half2 h0 = __floats2half2_rn(pf[t].x, pf[t].y);
            half2 h1 = __floats2half2_rn(pf[t].z, pf[t].w);
            uint2 u;
            u.x = h2_bits(h0);
            u.y = h2_bits(h1);
            *reinterpret_cast<uint2*>(abuf + row * LDAH + q * 4) = u;
        }

        // ---- prefetch next tile (overlaps MMA + epilogue) ----
        int wtn = wt + gstride;
        if (wtn < nwt) {
            #pragma unroll
            for (int t = 0; t < 4; t++) {
                int slot = lane + 32 * t;
                int row = slot >> 3;
                pf[t] = make_float4(0.f, 0.f, 0.f, 0.f);
                if (wtn * 16 + row < n) pf[t] = xg[(size_t)wtn * 128 + slot];
            }
        }
        __syncwarp();

        // ---- GEMM: 2 k-steps (K=16 each), 4 n-tiles, B in registers ----
        wmma::fragment<wmma::accumulator, 16, 16, 16, float> acc[4];
        #pragma unroll
        for (int nt = 0; nt < 4; nt++) wmma::fill_fragment(acc[nt], 0.0f);

        #pragma unroll
        for (int k = 0; k < 2; k++) {
            wmma::fragment<wmma::matrix_a, 16, 16, 16, half, wmma::row_major> af;
            wmma::load_matrix_sync(af, abuf + k * 16, LDAH);
            #pragma unroll
            for (int nt = 0; nt < 4; nt++)
                wmma::mma_sync(acc[nt], af, bf[k][nt], acc[nt]);
        }
        __syncwarp();

        // ---- bulk store D (16x64, f32) ----
        #pragma unroll
        for (int nt = 0; nt < 4; nt++)
            wmma::store_matrix_sync(dbuf + nt * 16, acc[nt], LDD,
                                    wmma::mem_row_major);
        __syncwarp();

        // ---- epilogue: lane pair per row, 4 independent accumulators ----
        float s0 = 0.f, s1 = 0.f, s2 = 0.f, s3 = 0.f;
        const float* rp = dbuf + erow * LDD + ehalf * 32;
        #pragma unroll
        for (int j4 = 0; j4 < 8; j4++) {
            float4 d = *reinterpret_cast<const float4*>(rp + j4 * 4);
            int j = ehalf * 32 + j4 * 4;
            float2 bw;
            float* sacc = (j4 & 3) == 0 ? &s0 : (j4 & 3) == 1 ? &s1
                        : (j4 & 3) == 2 ? &s2 : &s3;
            bw = sBW[j + 0]; *sacc = fmaf(fmaxf(d.x + bw.x, 0.f), bw.y, *sacc);
            bw = sBW[j + 1]; *sacc = fmaf(fmaxf(d.y + bw.x, 0.f), bw.y, *sacc);
            bw = sBW[j + 2]; *sacc = fmaf(fmaxf(d.z + bw.x, 0.f), bw.y, *sacc);
            bw = sBW[j + 3]; *sacc = fmaf(fmaxf(d.w + bw.x, 0.f), bw.y, *sacc);
        }
        float s = (s0 + s1) + (s2 + s3);
        s += __shfl_xor_sync(0xFFFFFFFF, s, 1);

        // ---- warp-segmented reduction over sorted bag ids ----
        float sv = __shfl_sync(0xFFFFFFFF, s, (lane & 15) << 1);
        int   row   = row0 + (lane & 15);
        bool  valid = (lane < 16) && (row < n);
        int   bag   = valid ? ids[row] : INT_MAX;
        float cv    = valid ? 1.0f : 0.0f;
        if (!valid) sv = 0.0f;

        #pragma unroll
        for (int d = 1; d < 16; d <<= 1) {
            float ts = __shfl_up_sync(0xFFFFFFFF, sv, d);
            float tc = __shfl_up_sync(0xFFFFFFFF, cv, d);
            int   tb = __shfl_up_sync(0xFFFFFFFF, bag, d);
            if (lane >= d && tb == bag) { sv += ts; cv += tc; }
        }
        int bnext = __shfl_down_sync(0xFFFFFFFF, bag, 1);
        if (valid && (lane == 15 || bnext != bag)) {
            atomicAdd(&g_sum[bag], sv);
            atomicAdd(&g_cnt[bag], cv);
        }
        __syncwarp();
        pb ^= 1;
    }
}

__global__ void finalize_kernel(float* __restrict__ out,
                                const float* __restrict__ b2, int nbags)
{
    int b = blockIdx.x * blockDim.x + threadIdx.x;
    if (b < nbags) {
        float c = g_cnt[b];
        c = (c > 0.0f) ? c : 1.0f;
        out[b] = g_sum[b] / c + b2[0];
    }
}

extern "C" void kernel_launch(void* const* d_in, const int* in_sizes, int n_in,
                              void* d_out, int out_size)
{
    const float* x   = (const float*)d_in[0];
    const int*   ids = (const int*)  d_in[1];
    const float* W1  = (const float*)d_in[2];
    const float* b1  = (const float*)d_in[3];
    const float* W2  = (const float*)d_in[4];
    const float* b2  = (const float*)d_in[5];
    float* out = (float*)d_out;

    int n     = in_sizes[1];
    int nbags = out_size;
    int nwt   = (n + 15) / 16;

    zero_kernel<<<(nbags + 255) / 256, 256>>>(nbags);

    int grid = 148 * 4;
    int maxg = (nwt + NWARP - 1) / NWARP;
    if (grid > maxg) grid = maxg;
    mlp_wmma_kernel<<<grid, 32 * NWARP>>>(x, ids, W1, b1, W2, n, nwt);

    finalize_kernel<<<(nbags + 255) / 256, 256>>>(out, b2, nbags);
}